// round 15
// baseline (speedup 1.0000x reference)
#include <cuda_runtime.h>
#include <cuda_bf16.h>
#include <cuda_fp16.h>
#include <mma.h>
#include <cstdint>

using namespace nvcuda;
typedef __nv_bfloat16 bf16;

#define BATCH 4
#define SEQ   4096
#define DIM   512
#define ROWS  16384
#define ATTN_SCALE 0.125f
#define EXP_SHIFT 11.0f
#define LN_EPS 1e-5f

/* ---------------- scratch (no allocations allowed) ---------------- */
__device__ __align__(256) float g_q [(size_t)ROWS * DIM];
__device__ __align__(256) float g_kv[(size_t)ROWS * 2 * DIM];
__device__ __align__(256) float g_rs[(size_t)BATCH * SEQ];

__device__ __align__(256) __half g_xh [(size_t)ROWS * DIM];
__device__ __align__(256) __half g_xl [(size_t)ROWS * DIM];
__device__ __align__(256) __half g_ch [(size_t)ROWS * DIM];
__device__ __align__(256) __half g_cl [(size_t)ROWS * DIM];
__device__ __align__(256) __half g_wqt [DIM * DIM];
__device__ __align__(256) __half g_wkvt[2 * DIM * DIM];
__device__ __align__(256) __half g_wot [DIM * DIM];
__device__ __align__(256) __half g_oh [(size_t)ROWS * DIM];
__device__ __align__(256) __half g_ol [(size_t)ROWS * DIM];

__device__ __align__(256) __half g_qh [(size_t)ROWS * DIM];
__device__ __align__(256) __half g_kh [(size_t)ROWS * DIM];
__device__ __align__(256) __half g_vt [(size_t)BATCH * DIM * SEQ];
__device__ __align__(256) __half g_ph [(size_t)BATCH * SEQ * SEQ];

/* ---------------- cp.async helpers ---------------- */
__device__ __forceinline__ unsigned smem_u32(const void* p) {
    return (unsigned)__cvta_generic_to_shared(p);
}
#define CPA16(dst, src) \
    asm volatile("cp.async.cg.shared.global [%0], [%1], 16;\n" :: "r"(dst), "l"(src))
#define CPCOMMIT() asm volatile("cp.async.commit_group;\n" ::)
template<int N> __device__ __forceinline__ void cpwait() {
    asm volatile("cp.async.wait_group %0;\n" :: "n"(N));
}

#define NT 256

/* ================= narrow GEMM (projections) =================
 * 128x128 tile, BK=32, PASSES=2 ((Ah+Al)Bh), 2 CTAs/SM, 3-stage.
 * EPI0 direct store; BIAS via smem epilogue.
 */
#define BM 128
#define BN 128

template<typename T, int BKT>
__device__ __forceinline__ void stage_tile(unsigned sm, const T* g, int ld, int tid) {
    constexpr int CPR = BKT / 8;
    constexpr int AST = BKT + 8;
    #pragma unroll
    for (int i = 0; i < (128 * CPR) / NT; i++) {
        int idx = i * NT + tid;
        int r = idx / CPR, c = (idx % CPR) * 8;
        CPA16(sm + (unsigned)(r * AST + c) * 2, g + (size_t)r * ld + c);
    }
}

template<bool BIAS>
__global__ __launch_bounds__(NT, 2) void gemm_proj(
    const __half* __restrict__ Ah, const __half* __restrict__ Al,
    const __half* __restrict__ Bh, float* __restrict__ C,
    const float* __restrict__ bias,
    int K, int lda, int ldb, int ldc)
{
    extern __shared__ char smem[];
    constexpr int BKT = 32;
    constexpr int AST = 40;
    constexpr unsigned TSZ = 128u * AST * 2u;
    constexpr unsigned STG = 3u * TSZ;

    const int tid  = threadIdx.x;
    const int warp = tid >> 5;
    const int wm = warp >> 2, wn = warp & 3;
    const int m0 = blockIdx.y * BM;
    const int n0 = blockIdx.x * BN;
    const unsigned sb0 = smem_u32(smem);

    const __half* gAh = Ah + (size_t)m0 * lda;
    const __half* gAl = Al + (size_t)m0 * lda;
    const __half* gBh = Bh + (size_t)n0 * ldb;

    wmma::fragment<wmma::accumulator, 16, 16, 16, float> acc[4][2];
    #pragma unroll
    for (int i = 0; i < 4; i++)
        #pragma unroll
        for (int j = 0; j < 2; j++)
            wmma::fill_fragment(acc[i][j], 0.0f);

    auto stage = [&](int s, int k0) {
        unsigned sp = sb0 + (unsigned)s * STG;
        stage_tile<__half, BKT>(sp, gAh + k0, lda, tid);
        stage_tile<__half, BKT>(sp + TSZ, gAl + k0, lda, tid);
        stage_tile<__half, BKT>(sp + 2u * TSZ, gBh + k0, ldb, tid);
        CPCOMMIT();
    };

    const int Cn = K / BKT;
    stage(0, 0);
    if (Cn > 1) stage(1, BKT);

    int s = 0;
    for (int i = 0; i < Cn; i++) {
        if (i + 2 < Cn) {
            int s2 = s + 2; if (s2 >= 3) s2 -= 3;
            stage(s2, (i + 2) * BKT);
            cpwait<2>();
        } else if (i + 1 < Cn) cpwait<1>();
        else cpwait<0>();
        __syncthreads();

        __half* sAh = (__half*)(smem + s * STG);
        __half* sAl = (__half*)(smem + s * STG + TSZ);
        __half* sBh = (__half*)(smem + s * STG + 2 * TSZ);

        #pragma unroll
        for (int kk = 0; kk < BKT; kk += 16) {
            wmma::fragment<wmma::matrix_a, 16, 16, 16, __half, wmma::row_major> a[4];
            wmma::fragment<wmma::matrix_b, 16, 16, 16, __half, wmma::col_major> bh[2];
            #pragma unroll
            for (int i2 = 0; i2 < 4; i2++)
                wmma::load_matrix_sync(a[i2], sAh + (wm * 64 + i2 * 16) * AST + kk, AST);
            #pragma unroll
            for (int j = 0; j < 2; j++)
                wmma::load_matrix_sync(bh[j], sBh + (wn * 32 + j * 16) * AST + kk, AST);
            #pragma unroll
            for (int i2 = 0; i2 < 4; i2++)
                #pragma unroll
                for (int j = 0; j < 2; j++)
                    wmma::mma_sync(acc[i2][j], a[i2], bh[j], acc[i2][j]);
            #pragma unroll
            for (int i2 = 0; i2 < 4; i2++)
                wmma::load_matrix_sync(a[i2], sAl + (wm * 64 + i2 * 16) * AST + kk, AST);
            #pragma unroll
            for (int i2 = 0; i2 < 4; i2++)
                #pragma unroll
                for (int j = 0; j < 2; j++)
                    wmma::mma_sync(acc[i2][j], a[i2], bh[j], acc[i2][j]);
        }
        __syncthreads();
        s = (s + 1 == 3) ? 0 : s + 1;
    }

    if (!BIAS) {
        #pragma unroll
        for (int i = 0; i < 4; i++)
            #pragma unroll
            for (int j = 0; j < 2; j++)
                wmma::store_matrix_sync(
                    C + (size_t)(m0 + wm * 64 + i * 16) * ldc + n0 + wn * 32 + j * 16,
                    acc[i][j], ldc, wmma::mem_row_major);
        return;
    }

    float* cs = (float*)smem;
    #pragma unroll
    for (int i = 0; i < 4; i++)
        #pragma unroll
        for (int j = 0; j < 2; j++)
            wmma::store_matrix_sync(cs + (wm * 64 + i * 16) * 132 + wn * 32 + j * 16,
                                    acc[i][j], 132, wmma::mem_row_major);
    __syncthreads();
    #pragma unroll
    for (int it = 0; it < 16; it++) {
        int idx = it * NT + tid;
        int r = idx >> 5, c4 = (idx & 31) * 4;
        float4 v = *(float4*)(cs + r * 132 + c4);
        v.x += bias[n0 + c4 + 0];
        v.y += bias[n0 + c4 + 1];
        v.z += bias[n0 + c4 + 2];
        v.w += bias[n0 + c4 + 3];
        *(float4*)(C + (size_t)(m0 + r) * ldc + n0 + c4) = v;
    }
}

/* ================= wide GEMM (attention, 1 pass) =================
 * 128x256 tile, BK=64, 8 warps of 64x64, 3-stage, 1 CTA/SM.
 * EPI: 2 = exp->fp16 + rowsum; 3 = /rowsum -> fp16 hi/lo.
 */
#define WBN 256
#define WKT 64
#define WAST 72

template<int RWS>
__device__ __forceinline__ void stage_tile_w(unsigned sm, const __half* g, int ld, int tid) {
    #pragma unroll
    for (int i = 0; i < RWS / 32; i++) {          /* RWS rows x 8 chunks / 256 thr */
        int idx = i * NT + tid;
        int r = idx >> 3, c = (idx & 7) * 8;
        CPA16(sm + (unsigned)(r * WAST + c) * 2, g + (size_t)r * ld + c);
    }
}

template<int EPI>
__global__ __launch_bounds__(NT, 1) void gemm_attn(
    const __half* __restrict__ A, const __half* __restrict__ B,
    __half* __restrict__ Ch, __half* __restrict__ Cl,
    __half* __restrict__ Hout, float* __restrict__ rs,
    int K, int lda, int ldb, int ldc,
    long long sA, long long sB, long long sC, float alpha)
{
    extern __shared__ char smem[];
    constexpr unsigned TA = 128u * WAST * 2u;     /* 18432 */
    constexpr unsigned TB = 256u * WAST * 2u;     /* 36864 */
    constexpr unsigned STG = TA + TB;             /* 55296 */

    const int tid  = threadIdx.x;
    const int warp = tid >> 5;
    const int wm = warp >> 2, wn = warp & 3;
    const int m0 = blockIdx.y * BM;
    const int n0 = blockIdx.x * WBN;
    const long long zb = blockIdx.z;
    const unsigned sb0 = smem_u32(smem);

    const __half* gA = A + zb * sA + (size_t)m0 * lda;
    const __half* gB = B + zb * sB + (size_t)n0 * ldb;

    wmma::fragment<wmma::accumulator, 16, 16, 16, float> acc[4][4];
    #pragma unroll
    for (int i = 0; i < 4; i++)
        #pragma unroll
        for (int j = 0; j < 4; j++)
            wmma::fill_fragment(acc[i][j], 0.0f);

    auto stage = [&](int s, int k0) {
        unsigned sp = sb0 + (unsigned)s * STG;
        stage_tile_w<128>(sp,      gA + k0, lda, tid);
        stage_tile_w<256>(sp + TA, gB + k0, ldb, tid);
        CPCOMMIT();
    };

    const int Cn = K / WKT;
    stage(0, 0);
    if (Cn > 1) stage(1, WKT);

    int s = 0;
    for (int i = 0; i < Cn; i++) {
        if (i + 2 < Cn) {
            int s2 = s + 2; if (s2 >= 3) s2 -= 3;
            stage(s2, (i + 2) * WKT);
            cpwait<2>();
        } else if (i + 1 < Cn) cpwait<1>();
        else cpwait<0>();
        __syncthreads();

        __half* sA = (__half*)(smem + s * STG);
        __half* sB = (__half*)(smem + s * STG + TA);

        #pragma unroll
        for (int kk = 0; kk < WKT; kk += 16) {
            wmma::fragment<wmma::matrix_a, 16, 16, 16, __half, wmma::row_major> a[4];
            wmma::fragment<wmma::matrix_b, 16, 16, 16, __half, wmma::col_major> b[4];
            #pragma unroll
            for (int i2 = 0; i2 < 4; i2++)
                wmma::load_matrix_sync(a[i2], sA + (wm * 64 + i2 * 16) * WAST + kk, WAST);
            #pragma unroll
            for (int j = 0; j < 4; j++)
                wmma::load_matrix_sync(b[j], sB + (wn * 64 + j * 16) * WAST + kk, WAST);
            #pragma unroll
            for (int i2 = 0; i2 < 4; i2++)
                #pragma unroll
                for (int j = 0; j < 4; j++)
                    wmma::mma_sync(acc[i2][j], a[i2], b[j], acc[i2][j]);
        }
        __syncthreads();
        s = (s + 1 == 3) ? 0 : s + 1;
    }

    /* alpha */
    if (EPI == 2) {
        #pragma unroll
        for (int i = 0; i < 4; i++)
            #pragma unroll
            for (int j = 0; j < 4; j++)
                #pragma unroll
                for (int t = 0; t < acc[i][j].num_elements; t++)
                    acc[i][j].x[t] *= alpha;
    }

    /* two-half epilogue through smem (64 x 264 fp32) */
    float* cs = (float*)smem;
    #pragma unroll
    for (int half = 0; half < 2; half++) {
        if (wm == half) {
            #pragma unroll
            for (int i = 0; i < 4; i++)
                #pragma unroll
                for (int j = 0; j < 4; j++)
                    wmma::store_matrix_sync(cs + (i * 16) * 264 + wn * 64 + j * 16,
                                            acc[i][j], 264, wmma::mem_row_major);
        }
        __syncthreads();

        #pragma unroll
        for (int it = 0; it < 16; it++) {
            int idx = it * NT + tid;          /* 64 x 64 float4 slots */
            int r = idx >> 6, c4 = (idx & 63) * 4;
            float4 v = *(float4*)(cs + r * 264 + c4);
            int gm = m0 + half * 64 + r;
            size_t base = (size_t)zb * sC + (size_t)gm * ldc + n0 + c4;

            if (EPI == 2) {
                float e0 = __expf(v.x - EXP_SHIFT);
                float e1 = __expf(v.y - EXP_SHIFT);
                float e2 = __expf(v.z - EXP_SHIFT);
                float e3 = __expf(v.w - EXP_SHIFT);
                __half2 t;
                t.x = __float2half(e0); t.y = __float2half(e1);
                *(__half2*)(Hout + base) = t;
                t.x = __float2half(e2); t.y = __float2half(e3);
                *(__half2*)(Hout + base + 2) = t;
                float s4 = (e0 + e1) + (e2 + e3);
                #pragma unroll
                for (int o = 16; o > 0; o >>= 1)
                    s4 += __shfl_xor_sync(0xffffffffu, s4, o);
                if ((tid & 31) == 0)
                    atomicAdd(&rs[(size_t)zb * SEQ + gm], s4);
            } else {
                float zi = __fdividef(1.0f, rs[(size_t)zb * SEQ + gm]);
                v.x *= zi; v.y *= zi; v.z *= zi; v.w *= zi;
                __half h0 = __float2half(v.x), h1 = __float2half(v.y);
                __half h2 = __float2half(v.z), h3 = __float2half(v.w);
                __half2 t;
                t.x = h0; t.y = h1; *(__half2*)(Ch + base) = t;
                t.x = h2; t.y = h3; *(__half2*)(Ch + base + 2) = t;
                t.x = __float2half(v.x - __half2float(h0));
                t.y = __float2half(v.y - __half2float(h1));
                *(__half2*)(Cl + base) = t;
                t.x = __float2half(v.z - __half2float(h2));
                t.y = __float2half(v.w - __half2float(h3));
                *(__half2*)(Cl + base + 2) = t;
            }
        }
        __syncthreads();
    }
}

/* ---------------- fused input split: x/ctx -> fp16 hi/lo ------------- */
__global__ __launch_bounds__(256) void split_inputs(
    const float* __restrict__ x, const float* __restrict__ ctx,
    __half* __restrict__ xh, __half* __restrict__ xl,
    __half* __restrict__ ch, __half* __restrict__ cl)
{
    const float* in = blockIdx.y ? ctx : x;
    __half* h = blockIdx.y ? ch : xh;
    __half* l = blockIdx.y ? cl : xl;
    size_t i = (size_t)blockIdx.x * 256 + threadIdx.x;
    float4 v = ((const float4*)in)[i];
    __half h0 = __float2half(v.x), h1 = __float2half(v.y);
    __half h2 = __float2half(v.z), h3 = __float2half(v.w);
    __half2 t;
    t.x = h0; t.y = h1; *(__half2*)(h + i * 4) = t;
    t.x = h2; t.y = h3; *(__half2*)(h + i * 4 + 2) = t;
    t.x = __float2half(v.x - __half2float(h0));
    t.y = __float2half(v.y - __half2float(h1));
    *(__half2*)(l + i * 4) = t;
    t.x = __float2half(v.z - __half2float(h2));
    t.y = __float2half(v.w - __half2float(h3));
    *(__half2*)(l + i * 4 + 2) = t;
}

/* ---------------- weights -> W^T fp16; tail zeroes rowsums ---------- */
__global__ __launch_bounds__(256) void wsplit_all(
    const float* __restrict__ Wq, const float* __restrict__ Wkv, const float* __restrict__ Wo,
    __half* __restrict__ wqt, __half* __restrict__ wkvt, __half* __restrict__ wot,
    float* __restrict__ rs)
{
    int bx = blockIdx.x;
    if (bx >= 1024) {
        rs[(bx - 1024) * 256 + threadIdx.x] = 0.0f;
        return;
    }
    __shared__ float t[32][33];
    const float* W; __half* th; int N, tidx;
    if (bx < 256)      { W = Wq;  th = wqt;  N = DIM;     tidx = bx;       }
    else if (bx < 768) { W = Wkv; th = wkvt; N = 2 * DIM; tidx = bx - 256; }
    else               { W = Wo;  th = wot;  N = DIM;     tidx = bx - 768; }
    int nT = N / 32;
    int n0 = (tidx % nT) * 32, k0 = (tidx / nT) * 32;
    int tx = threadIdx.x & 31, ty = threadIdx.x >> 5;
    #pragma unroll
    for (int j = 0; j < 4; j++) {
        int r = ty + j * 8;
        t[r][tx] = W[(size_t)(k0 + r) * N + n0 + tx];
    }
    __syncthreads();
    #pragma unroll
    for (int j = 0; j < 4; j++) {
        int r = ty + j * 8;
        th[(size_t)(n0 + r) * DIM + k0 + tx] = __float2half(t[tx][r]);
    }
}

/* ---------------- fused attention prep ---------------- */
__global__ __launch_bounds__(256) void prep_attn(
    const float* __restrict__ q, const float* __restrict__ kv,
    const float* __restrict__ g, const float* __restrict__ b,
    __half* __restrict__ qh, __half* __restrict__ kh, __half* __restrict__ vt)
{
    const int mode = blockIdx.y;
    int tid = threadIdx.x;

    if (mode == 2) {
        if (blockIdx.x >= 8192) return;
        __shared__ float t[32][33];
        int bx = blockIdx.x;
        int bb = bx >> 11;
        int rem = bx & 2047;
        int d0 = (rem >> 7) * 32;
        int m0 = (rem & 127) * 32;
        int tx = tid & 31, ty = tid >> 5;
        const float* src = kv + ((size_t)bb * SEQ) * (2 * DIM) + DIM;
        #pragma unroll
        for (int j = 0; j < 4; j++) {
            int r = ty + j * 8;
            t[r][tx] = src[(size_t)(m0 + r) * (2 * DIM) + d0 + tx];
        }
        __syncthreads();
        #pragma unroll
        for (int j = 0; j < 4; j++) {
            int r = ty + j * 8;
            vt[((size_t)bb * DIM + d0 + r) * SEQ + m0 + tx] = __float2half(t[tx][r]);
        }
        return;
    }

    __shared__ float red[16];
    const float* row = (mode == 0) ? q + (size_t)blockIdx.x * DIM
                                   : kv + (size_t)blockIdx.x * (2 * DIM);
    float x0 = row[tid];
    float x1 = row[tid + 256];
    float s  = x0 + x1;
    float sq = x0 * x0 + x1 * x1;
    #pragma unroll
    for (int o = 16; o > 0; o >>= 1) {
        s  += __shfl_xor_sync(0xffffffffu, s,  o);
        sq += __shfl_xor_sync(0xffffffffu, sq, o);
    }
    if ((tid & 31) == 0) { red[tid >> 5] = s; red[8 + (tid >> 5)] = sq; }
    __syncthreads();
    if (tid < 32) {
        float vs = (tid < 8) ? red[tid] : 0.0f;
        float vq = (tid < 8) ? red[8 + tid] : 0.0f;
        #pragma unroll
        for (int o = 4; o > 0; o >>= 1) {
            vs += __shfl_xor_sync(0xffffffffu, vs, o);
            vq += __shfl_xor_sync(0xffffffffu, vq, o);
        }
        if (tid == 0) { red[0] = vs; red[1] = vq; }
    }
    __syncthreads();
    float mean = red[0] * (1.0f / 512.0f);
    float var  = red[1] * (1.0f / 512.0f) - mean * mean;
    float rstd = rsqrtf(var + LN_EPS);
    float y0 = (x0 - mean) * rstd * g[tid]       + b[tid];
    float y1 = (x1 - mean) * rstd * g[tid + 256] + b[tid + 256];
    __half* hr = (mode == 0) ? qh + (size_t)blockIdx.x * DIM
                             : kh + (size_t)blockIdx.x * DIM;
    hr[tid]       = __float2half(y0);
    hr[tid + 256] = __float2half(y1);
}

/* ---------------- launcher ---------------- */
#define SMEM_P 92160u      /* proj: 3 stages x 3 tiles (BK=32)     */
#define SMEM_W 165888u     /* attn wide: 3 stages x (A+B) (BK=64)  */

extern "C" void kernel_launch(void* const* d_in, const int* in_sizes, int n_in,
                              void* d_out, int out_size)
{
    const float* x    = (const float*)d_in[0];
    const float* ctx  = (const float*)d_in[1];
    const float* Wq   = (const float*)d_in[2];
    const float* Wkv  = (const float*)d_in[3];
    const float* Wo   = (const float*)d_in[4];
    const float* bo   = (const float*)d_in[5];
    const float* ln_g = (const float*)d_in[6];
    const float* ln_b = (const float*)d_in[7];
    float* out = (float*)d_out;

    float *q, *kv, *rs;
    __half *xh, *xl, *ch, *cl, *wqt, *wkvt, *wot, *oh, *ol, *qh, *kh, *vt, *ph;
    cudaGetSymbolAddress((void**)&q,    g_q);
    cudaGetSymbolAddress((void**)&kv,   g_kv);
    cudaGetSymbolAddress((void**)&rs,   g_rs);
    cudaGetSymbolAddress((void**)&xh,   g_xh);    cudaGetSymbolAddress((void**)&xl,   g_xl);
    cudaGetSymbolAddress((void**)&ch,   g_ch);    cudaGetSymbolAddress((void**)&cl,   g_cl);
    cudaGetSymbolAddress((void**)&wqt,  g_wqt);   cudaGetSymbolAddress((void**)&wkvt, g_wkvt);
    cudaGetSymbolAddress((void**)&wot,  g_wot);
    cudaGetSymbolAddress((void**)&oh,   g_oh);    cudaGetSymbolAddress((void**)&ol,   g_ol);
    cudaGetSymbolAddress((void**)&qh,   g_qh);    cudaGetSymbolAddress((void**)&kh,   g_kh);
    cudaGetSymbolAddress((void**)&vt,   g_vt);    cudaGetSymbolAddress((void**)&ph,   g_ph);

    cudaFuncSetAttribute(gemm_proj<false>,
                         cudaFuncAttributeMaxDynamicSharedMemorySize, SMEM_P);
    cudaFuncSetAttribute(gemm_proj<true>,
                         cudaFuncAttributeMaxDynamicSharedMemorySize, SMEM_P);
    cudaFuncSetAttribute(gemm_attn<2>,
                         cudaFuncAttributeMaxDynamicSharedMemorySize, SMEM_W);
    cudaFuncSetAttribute(gemm_attn<3>,
                         cudaFuncAttributeMaxDynamicSharedMemorySize, SMEM_W);

    /* 0: split inputs to fp16 hi/lo */
    split_inputs<<<dim3(ROWS * DIM / 4 / 256, 2), 256>>>(x, ctx, xh, xl, ch, cl);
    /* 1: weights -> fp16 transpose (+ zero rowsums) */
    wsplit_all<<<1088, 256>>>(Wq, Wkv, Wo, wqt, wkvt, wot, rs);

    /* 2: q = x @ Wq */
    gemm_proj<false><<<dim3(DIM / BN, ROWS / BM), NT, SMEM_P>>>(
        xh, xl, wqt, q, nullptr, DIM, DIM, DIM, DIM);

    /* 3: kv = ctx @ Wkv */
    gemm_proj<false><<<dim3(2 * DIM / BN, ROWS / BM), NT, SMEM_P>>>(
        ch, cl, wkvt, kv, nullptr, DIM, DIM, DIM, 2 * DIM);

    /* 4: LN(q)->fp16, LN(k)->fp16, v->v^T fp16 */
    prep_attn<<<dim3(ROWS, 3), 256>>>(q, kv, ln_g, ln_b, qh, kh, vt);

    /* 5: expS = exp(scale * q@k^T - 11) -> fp16 + rowsums (wide) */
    gemm_attn<2><<<dim3(SEQ / WBN, SEQ / BM, BATCH), NT, SMEM_W>>>(
        qh, kh, nullptr, nullptr, ph, rs,
        DIM, DIM, DIM, SEQ,
        (long long)SEQ * DIM, (long long)SEQ * DIM, (long long)SEQ * SEQ, ATTN_SCALE);

    /* 6: O = (expS @ v) / Z -> fp16 hi/lo (wide) */
    gemm_attn<3><<<dim3(DIM / WBN, SEQ / BM, BATCH), NT, SMEM_W>>>(
        ph, vt, oh, ol, nullptr, rs,
        SEQ, SEQ, SEQ, DIM,
        (long long)SEQ * SEQ, (long long)DIM * SEQ, (long long)SEQ * DIM, 1.0f);

    /* 7: out = O @ Wo + bo */
    gemm_proj<true><<<dim3(DIM / BN, ROWS / BM), NT, SMEM_P>>>(
        oh, ol, wot, out, bo, DIM, DIM, DIM, DIM);
}

// round 16
// speedup vs baseline: 1.0946x; 1.0946x over previous
#include <cuda_runtime.h>
#include <cuda_bf16.h>
#include <cuda_fp16.h>
#include <mma.h>
#include <cstdint>

using namespace nvcuda;
typedef __nv_bfloat16 bf16;

#define BATCH 4
#define SEQ   4096
#define DIM   512
#define ROWS  16384
#define ATTN_SCALE 0.125f
#define EXP_SHIFT 11.0f
#define LN_EPS 1e-5f

/* ---------------- scratch (no allocations allowed) ---------------- */
__device__ __align__(256) float g_q [(size_t)ROWS * DIM];
__device__ __align__(256) float g_kv[(size_t)ROWS * 2 * DIM];
__device__ __align__(256) float g_rs[(size_t)BATCH * SEQ];    /* softmax row sums */

__device__ __align__(256) __half g_xh [(size_t)ROWS * DIM];
__device__ __align__(256) __half g_xl [(size_t)ROWS * DIM];
__device__ __align__(256) __half g_ch [(size_t)ROWS * DIM];
__device__ __align__(256) __half g_cl [(size_t)ROWS * DIM];
__device__ __align__(256) __half g_wqt [DIM * DIM];
__device__ __align__(256) __half g_wkvt[2 * DIM * DIM];
__device__ __align__(256) __half g_wot [DIM * DIM];
__device__ __align__(256) __half g_oh [(size_t)ROWS * DIM];   /* O hi fp16 */
__device__ __align__(256) __half g_ol [(size_t)ROWS * DIM];   /* O lo fp16 */

__device__ __align__(256) __half g_qh [(size_t)ROWS * DIM];
__device__ __align__(256) __half g_kh [(size_t)ROWS * DIM];
__device__ __align__(256) __half g_vt [(size_t)BATCH * DIM * SEQ];
__device__ __align__(256) __half g_ph [(size_t)BATCH * SEQ * SEQ]; /* exp(S-11) fp16 */

/* ---------------- cp.async helpers ---------------- */
__device__ __forceinline__ unsigned smem_u32(const void* p) {
    return (unsigned)__cvta_generic_to_shared(p);
}
#define CPA16(dst, src) \
    asm volatile("cp.async.cg.shared.global [%0], [%1], 16;\n" :: "r"(dst), "l"(src))
#define CPCOMMIT() asm volatile("cp.async.commit_group;\n" ::)
template<int N> __device__ __forceinline__ void cpwait() {
    asm volatile("cp.async.wait_group %0;\n" :: "n"(N));
}

/* ---------------- hi/lo GEMM ----------------
 * C[M,N] = alpha * A @ B^T, B given [N,K] row-major.
 * PASSES: 2 = (Ah+Al)Bh; 1 = Ah Bh.
 * EPI: 0 = fp32 direct store (no bias) / smem+bias if BIAS;
 *      2 = exp->fp16 store + rowsum atomics;
 *      3 = divide-by-rowsum then fp16 hi/lo split store.
 * 128x128 tiles, BKT k-chunk, STAGES-deep cp.async pipeline,
 * 256 thr, 8 warps of 64x32, 2 CTAs/SM.
 */
#define BM 128
#define BN 128
#define NT  256

template<typename T, int BKT>
__device__ __forceinline__ void stage_tile(unsigned sm, const T* g, int ld, int tid) {
    constexpr int CPR = BKT / 8;
    constexpr int AST = BKT + 8;
    #pragma unroll
    for (int i = 0; i < (128 * CPR) / NT; i++) {
        int idx = i * NT + tid;
        int r = idx / CPR, c = (idx % CPR) * 8;
        CPA16(sm + (unsigned)(r * AST + c) * 2, g + (size_t)r * ld + c);
    }
}

template<typename T, int BKT, int PASSES, int STAGES, int EPI, bool BIAS>
__global__ __launch_bounds__(NT, 2) void gemm_hilo(
    const T* __restrict__ Ah, const T* __restrict__ Al,
    const T* __restrict__ Bh,
    float* __restrict__ C, __half* __restrict__ Ch, __half* __restrict__ Cl,
    __half* __restrict__ Hout, float* __restrict__ rs,
    const float* __restrict__ bias,
    int K, int lda, int ldb, int ldc,
    long long sA, long long sB, long long sC, float alpha)
{
    extern __shared__ char smem[];
    constexpr int AST = BKT + 8;
    constexpr unsigned TSZ = 128u * AST * 2u;
    constexpr unsigned NTILE = (PASSES == 2) ? 3u : 2u;
    constexpr unsigned STG = NTILE * TSZ;

    const int tid  = threadIdx.x;
    const int warp = tid >> 5;
    const int wm = warp >> 2;
    const int wn = warp & 3;
    const int m0 = blockIdx.y * BM;
    const int n0 = blockIdx.x * BN;
    const long long zb = blockIdx.z;
    const unsigned sb0 = smem_u32(smem);

    const T* gAh = Ah + zb * sA + (size_t)m0 * lda;
    const T* gAl = (PASSES >= 2) ? (Al + zb * sA + (size_t)m0 * lda) : nullptr;
    const T* gBh = Bh + zb * sB + (size_t)n0 * ldb;

    wmma::fragment<wmma::accumulator, 16, 16, 16, float> acc[4][2];
    #pragma unroll
    for (int i = 0; i < 4; i++)
        #pragma unroll
        for (int j = 0; j < 2; j++)
            wmma::fill_fragment(acc[i][j], 0.0f);

    auto stage = [&](int s, int k0) {
        unsigned sp = sb0 + (unsigned)s * STG;
        stage_tile<T, BKT>(sp, gAh + k0, lda, tid);
        stage_tile<T, BKT>(sp + (NTILE - 1u) * TSZ, gBh + k0, ldb, tid);
        if (PASSES >= 2) stage_tile<T, BKT>(sp + TSZ, gAl + k0, lda, tid);
        CPCOMMIT();
    };

    const int Cn = K / BKT;
    stage(0, 0);
    if (STAGES == 3 && Cn > 1) stage(1, BKT);

    int s = 0;
    for (int i = 0; i < Cn; i++) {
        if (STAGES == 3) {
            if (i + 2 < Cn) {
                int s2 = s + 2; if (s2 >= 3) s2 -= 3;
                stage(s2, (i + 2) * BKT);
                cpwait<2>();
            } else if (i + 1 < Cn) {
                cpwait<1>();
            } else {
                cpwait<0>();
            }
        } else {
            if (i + 1 < Cn) { stage(s ^ 1, (i + 1) * BKT); cpwait<1>(); }
            else            { cpwait<0>(); }
        }
        __syncthreads();

        T* sAh = (T*)(smem + s * STG);
        T* sAl = (T*)(smem + s * STG + TSZ);
        T* sBh = (T*)(smem + s * STG + (NTILE - 1u) * TSZ);

        #pragma unroll
        for (int kk = 0; kk < BKT; kk += 16) {
            wmma::fragment<wmma::matrix_a, 16, 16, 16, T, wmma::row_major> a[4];
            wmma::fragment<wmma::matrix_b, 16, 16, 16, T, wmma::col_major> bh[2];
            #pragma unroll
            for (int i2 = 0; i2 < 4; i2++)
                wmma::load_matrix_sync(a[i2], sAh + (wm * 64 + i2 * 16) * AST + kk, AST);
            #pragma unroll
            for (int j = 0; j < 2; j++)
                wmma::load_matrix_sync(bh[j], sBh + (wn * 32 + j * 16) * AST + kk, AST);

            #pragma unroll
            for (int i2 = 0; i2 < 4; i2++)
                #pragma unroll
                for (int j = 0; j < 2; j++)
                    wmma::mma_sync(acc[i2][j], a[i2], bh[j], acc[i2][j]);

            if (PASSES >= 2) {
                #pragma unroll
                for (int i2 = 0; i2 < 4; i2++)
                    wmma::load_matrix_sync(a[i2], sAl + (wm * 64 + i2 * 16) * AST + kk, AST);
                #pragma unroll
                for (int i2 = 0; i2 < 4; i2++)
                    #pragma unroll
                    for (int j = 0; j < 2; j++)
                        wmma::mma_sync(acc[i2][j], a[i2], bh[j], acc[i2][j]);
            }
        }
        __syncthreads();
        if (STAGES == 3) s = (s + 1 == 3) ? 0 : s + 1;
        else             s ^= 1;
    }

    if (EPI == 0 && !BIAS) {
        /* direct global store: no smem roundtrip, no extra syncs */
        #pragma unroll
        for (int i = 0; i < 4; i++)
            #pragma unroll
            for (int j = 0; j < 2; j++) {
                if (alpha != 1.0f)
                    #pragma unroll
                    for (int t = 0; t < acc[i][j].num_elements; t++)
                        acc[i][j].x[t] *= alpha;
                wmma::store_matrix_sync(
                    C + (size_t)zb * sC + (size_t)(m0 + wm * 64 + i * 16) * ldc
                      + n0 + wn * 32 + j * 16,
                    acc[i][j], ldc, wmma::mem_row_major);
            }
        return;
    }

    /* ---- epilogue via smem (128 x 132 fp32) ---- */
    float* cs = (float*)smem;
    #pragma unroll
    for (int i = 0; i < 4; i++)
        #pragma unroll
        for (int j = 0; j < 2; j++) {
            #pragma unroll
            for (int t = 0; t < acc[i][j].num_elements; t++)
                acc[i][j].x[t] *= alpha;
            wmma::store_matrix_sync(cs + (wm * 64 + i * 16) * 132 + wn * 32 + j * 16,
                                    acc[i][j], 132, wmma::mem_row_major);
        }
    __syncthreads();

    #pragma unroll
    for (int it = 0; it < 16; it++) {
        int idx = it * NT + tid;
        int r = idx >> 5, c4 = (idx & 31) * 4;   /* whole warp shares row r */
        float4 v = *(float4*)(cs + r * 132 + c4);

        if (EPI == 2) {
            float e0 = __expf(v.x - EXP_SHIFT);
            float e1 = __expf(v.y - EXP_SHIFT);
            float e2 = __expf(v.z - EXP_SHIFT);
            float e3 = __expf(v.w - EXP_SHIFT);
            size_t base = (size_t)zb * sC + (size_t)(m0 + r) * ldc + n0 + c4;
            __half2 t;
            t.x = __float2half(e0); t.y = __float2half(e1);
            *(__half2*)(Hout + base) = t;
            t.x = __float2half(e2); t.y = __float2half(e3);
            *(__half2*)(Hout + base + 2) = t;
            float s4 = (e0 + e1) + (e2 + e3);
            #pragma unroll
            for (int o = 16; o > 0; o >>= 1)
                s4 += __shfl_xor_sync(0xffffffffu, s4, o);
            if ((tid & 31) == 0)
                atomicAdd(&rs[(size_t)zb * SEQ + m0 + r], s4);
        } else if (EPI == 3) {
            float zi = __fdividef(1.0f, rs[(size_t)zb * SEQ + m0 + r]);
            v.x *= zi; v.y *= zi; v.z *= zi; v.w *= zi;
            size_t base = (size_t)zb * sC + (size_t)(m0 + r) * ldc + n0 + c4;
            __half h0 = __float2half(v.x), h1 = __float2half(v.y);
            __half h2 = __float2half(v.z), h3 = __float2half(v.w);
            __half2 t;
            t.x = h0; t.y = h1; *(__half2*)(Ch + base) = t;
            t.x = h2; t.y = h3; *(__half2*)(Ch + base + 2) = t;
            t.x = __float2half(v.x - __half2float(h0));
            t.y = __float2half(v.y - __half2float(h1));
            *(__half2*)(Cl + base) = t;
            t.x = __float2half(v.z - __half2float(h2));
            t.y = __float2half(v.w - __half2float(h3));
            *(__half2*)(Cl + base + 2) = t;
        } else {
            if (BIAS) {
                v.x += bias[n0 + c4 + 0];
                v.y += bias[n0 + c4 + 1];
                v.z += bias[n0 + c4 + 2];
                v.w += bias[n0 + c4 + 3];
            }
            size_t base = (size_t)zb * sC + (size_t)(m0 + r) * ldc + n0 + c4;
            *(float4*)(C + base) = v;
        }
    }
}

/* ---------------- fused input split: x/ctx -> fp16 hi/lo ------------- */
__global__ __launch_bounds__(256) void split_inputs(
    const float* __restrict__ x, const float* __restrict__ ctx,
    __half* __restrict__ xh, __half* __restrict__ xl,
    __half* __restrict__ ch, __half* __restrict__ cl)
{
    const float* in = blockIdx.y ? ctx : x;
    __half* h = blockIdx.y ? ch : xh;
    __half* l = blockIdx.y ? cl : xl;
    size_t i = (size_t)blockIdx.x * 256 + threadIdx.x;
    float4 v = ((const float4*)in)[i];
    __half h0 = __float2half(v.x), h1 = __float2half(v.y);
    __half h2 = __float2half(v.z), h3 = __float2half(v.w);
    __half2 t;
    t.x = h0; t.y = h1; *(__half2*)(h + i * 4) = t;
    t.x = h2; t.y = h3; *(__half2*)(h + i * 4 + 2) = t;
    t.x = __float2half(v.x - __half2float(h0));
    t.y = __float2half(v.y - __half2float(h1));
    *(__half2*)(l + i * 4) = t;
    t.x = __float2half(v.z - __half2float(h2));
    t.y = __float2half(v.w - __half2float(h3));
    *(__half2*)(l + i * 4 + 2) = t;
}

/* ---------------- weights -> W^T fp16 single; tail blocks zero rs -------- */
__global__ __launch_bounds__(256) void wsplit_all(
    const float* __restrict__ Wq, const float* __restrict__ Wkv, const float* __restrict__ Wo,
    __half* __restrict__ wqt, __half* __restrict__ wkvt, __half* __restrict__ wot,
    float* __restrict__ rs)
{
    int bx = blockIdx.x;
    if (bx >= 1024) {                  /* 64 tail blocks zero the rowsums */
        rs[(bx - 1024) * 256 + threadIdx.x] = 0.0f;
        return;
    }
    __shared__ float t[32][33];
    const float* W; __half* th; int N, tidx;
    if (bx < 256)      { W = Wq;  th = wqt;  N = DIM;     tidx = bx;       }
    else if (bx < 768) { W = Wkv; th = wkvt; N = 2 * DIM; tidx = bx - 256; }
    else               { W = Wo;  th = wot;  N = DIM;     tidx = bx - 768; }
    int nT = N / 32;
    int n0 = (tidx % nT) * 32, k0 = (tidx / nT) * 32;
    int tx = threadIdx.x & 31, ty = threadIdx.x >> 5;
    #pragma unroll
    for (int j = 0; j < 4; j++) {
        int r = ty + j * 8;
        t[r][tx] = W[(size_t)(k0 + r) * N + n0 + tx];
    }
    __syncthreads();
    #pragma unroll
    for (int j = 0; j < 4; j++) {
        int r = ty + j * 8;
        th[(size_t)(n0 + r) * DIM + k0 + tx] = __float2half(t[tx][r]);
    }
}

/* ---------------- fused attention prep ---------------- */
__global__ __launch_bounds__(256) void prep_attn(
    const float* __restrict__ q, const float* __restrict__ kv,
    const float* __restrict__ g, const float* __restrict__ b,
    __half* __restrict__ qh, __half* __restrict__ kh, __half* __restrict__ vt)
{
    const int mode = blockIdx.y;
    int tid = threadIdx.x;

    if (mode == 2) {                     /* v transpose, fp16 single */
        if (blockIdx.x >= 8192) return;
        __shared__ float t[32][33];
        int bx = blockIdx.x;
        int bb = bx >> 11;
        int rem = bx & 2047;
        int d0 = (rem >> 7) * 32;
        int m0 = (rem & 127) * 32;
        int tx = tid & 31, ty = tid >> 5;
        const float* src = kv + ((size_t)bb * SEQ) * (2 * DIM) + DIM;
        #pragma unroll
        for (int j = 0; j < 4; j++) {
            int r = ty + j * 8;
            t[r][tx] = src[(size_t)(m0 + r) * (2 * DIM) + d0 + tx];
        }
        __syncthreads();
        #pragma unroll
        for (int j = 0; j < 4; j++) {
            int r = ty + j * 8;
            vt[((size_t)bb * DIM + d0 + r) * SEQ + m0 + tx] = __float2half(t[tx][r]);
        }
        return;
    }

    __shared__ float red[16];
    const float* row = (mode == 0) ? q + (size_t)blockIdx.x * DIM
                                   : kv + (size_t)blockIdx.x * (2 * DIM);
    float x0 = row[tid];
    float x1 = row[tid + 256];
    float s  = x0 + x1;
    float sq = x0 * x0 + x1 * x1;
    #pragma unroll
    for (int o = 16; o > 0; o >>= 1) {
        s  += __shfl_xor_sync(0xffffffffu, s,  o);
        sq += __shfl_xor_sync(0xffffffffu, sq, o);
    }
    if ((tid & 31) == 0) { red[tid >> 5] = s; red[8 + (tid >> 5)] = sq; }
    __syncthreads();
    if (tid < 32) {
        float vs = (tid < 8) ? red[tid] : 0.0f;
        float vq = (tid < 8) ? red[8 + tid] : 0.0f;
        #pragma unroll
        for (int o = 4; o > 0; o >>= 1) {
            vs += __shfl_xor_sync(0xffffffffu, vs, o);
            vq += __shfl_xor_sync(0xffffffffu, vq, o);
        }
        if (tid == 0) { red[0] = vs; red[1] = vq; }
    }
    __syncthreads();
    float mean = red[0] * (1.0f / 512.0f);
    float var  = red[1] * (1.0f / 512.0f) - mean * mean;
    float rstd = rsqrtf(var + LN_EPS);
    float y0 = (x0 - mean) * rstd * g[tid]       + b[tid];
    float y1 = (x1 - mean) * rstd * g[tid + 256] + b[tid + 256];
    __half* hr = (mode == 0) ? qh + (size_t)blockIdx.x * DIM
                             : kh + (size_t)blockIdx.x * DIM;
    hr[tid]       = __float2half(y0);
    hr[tid + 256] = __float2half(y1);
}

/* ---------------- launcher ---------------- */
#define SMEM_P 110592u     /* proj: 2 stages x 3 tiles (BK=64)  */
#define SMEM_A 110592u     /* attn: 3 stages x 2 tiles (BK=64)  */

extern "C" void kernel_launch(void* const* d_in, const int* in_sizes, int n_in,
                              void* d_out, int out_size)
{
    const float* x    = (const float*)d_in[0];
    const float* ctx  = (const float*)d_in[1];
    const float* Wq   = (const float*)d_in[2];
    const float* Wkv  = (const float*)d_in[3];
    const float* Wo   = (const float*)d_in[4];
    const float* bo   = (const float*)d_in[5];
    const float* ln_g = (const float*)d_in[6];
    const float* ln_b = (const float*)d_in[7];
    float* out = (float*)d_out;

    float *q, *kv, *rs;
    __half *xh, *xl, *ch, *cl, *wqt, *wkvt, *wot, *oh, *ol, *qh, *kh, *vt, *ph;
    cudaGetSymbolAddress((void**)&q,    g_q);
    cudaGetSymbolAddress((void**)&kv,   g_kv);
    cudaGetSymbolAddress((void**)&rs,   g_rs);
    cudaGetSymbolAddress((void**)&xh,   g_xh);    cudaGetSymbolAddress((void**)&xl,   g_xl);
    cudaGetSymbolAddress((void**)&ch,   g_ch);    cudaGetSymbolAddress((void**)&cl,   g_cl);
    cudaGetSymbolAddress((void**)&wqt,  g_wqt);   cudaGetSymbolAddress((void**)&wkvt, g_wkvt);
    cudaGetSymbolAddress((void**)&wot,  g_wot);
    cudaGetSymbolAddress((void**)&oh,   g_oh);    cudaGetSymbolAddress((void**)&ol,   g_ol);
    cudaGetSymbolAddress((void**)&qh,   g_qh);    cudaGetSymbolAddress((void**)&kh,   g_kh);
    cudaGetSymbolAddress((void**)&vt,   g_vt);    cudaGetSymbolAddress((void**)&ph,   g_ph);

    cudaFuncSetAttribute(gemm_hilo<__half,64, 2, 2, 0, false>,
                         cudaFuncAttributeMaxDynamicSharedMemorySize, SMEM_P);
    cudaFuncSetAttribute(gemm_hilo<__half,64, 2, 2, 0, true>,
                         cudaFuncAttributeMaxDynamicSharedMemorySize, SMEM_P);
    cudaFuncSetAttribute(gemm_hilo<__half,64, 1, 3, 2, false>,
                         cudaFuncAttributeMaxDynamicSharedMemorySize, SMEM_A);
    cudaFuncSetAttribute(gemm_hilo<__half,64, 1, 3, 3, false>,
                         cudaFuncAttributeMaxDynamicSharedMemorySize, SMEM_A);

    /* 0: split inputs to fp16 hi/lo */
    split_inputs<<<dim3(ROWS * DIM / 4 / 256, 2), 256>>>(x, ctx, xh, xl, ch, cl);
    /* 1: weights -> fp16 transpose (+ zero rowsums in tail blocks) */
    wsplit_all<<<1088, 256>>>(Wq, Wkv, Wo, wqt, wkvt, wot, rs);

    /* 2: q = x @ Wq (fp16x2, BK=64, 2-stage, direct store) */
    gemm_hilo<__half,64,2,2,0,false><<<dim3(DIM / BN, ROWS / BM, 1), NT, SMEM_P>>>(
        xh, xl, wqt, q, nullptr, nullptr, nullptr, nullptr, nullptr,
        DIM, DIM, DIM, DIM, 0, 0, 0, 1.0f);

    /* 3: kv = ctx @ Wkv (fp16x2, BK=64, 2-stage, direct store) */
    gemm_hilo<__half,64,2,2,0,false><<<dim3(2 * DIM / BN, ROWS / BM, 1), NT, SMEM_P>>>(
        ch, cl, wkvt, kv, nullptr, nullptr, nullptr, nullptr, nullptr,
        DIM, DIM, DIM, 2 * DIM, 0, 0, 0, 1.0f);

    /* 4: LN(q)->fp16, LN(k)->fp16, v->v^T fp16 */
    prep_attn<<<dim3(ROWS, 3), 256>>>(q, kv, ln_g, ln_b, qh, kh, vt);

    /* 5: expS = exp(scale * q @ k^T - 11) -> fp16 + row sums */
    gemm_hilo<__half,64,1,3,2,false><<<dim3(SEQ / BN, SEQ / BM, BATCH), NT, SMEM_A>>>(
        qh, nullptr, kh, nullptr, nullptr, nullptr, ph, rs, nullptr,
        DIM, DIM, DIM, SEQ,
        (long long)SEQ * DIM, (long long)SEQ * DIM, (long long)SEQ * SEQ, ATTN_SCALE);

    /* 6: O = (expS @ v) / Z -> fp16 hi/lo */
    gemm_hilo<__half,64,1,3,3,false><<<dim3(DIM / BN, SEQ / BM, BATCH), NT, SMEM_A>>>(
        ph, nullptr, vt, nullptr, oh, ol, nullptr, rs, nullptr,
        SEQ, SEQ, SEQ, DIM,
        (long long)SEQ * SEQ, (long long)DIM * SEQ, (long long)SEQ * DIM, 1.0f);

    /* 7: out = O @ Wo + bo (fp16x2, BK=64, 2-stage, smem epilogue for bias) */
    gemm_hilo<__half,64,2,2,0,true><<<dim3(DIM / BN, ROWS / BM, 1), NT, SMEM_P>>>(
        oh, ol, wot, out, nullptr, nullptr, nullptr, nullptr, bo,
        DIM, DIM, DIM, DIM, 0, 0, 0, 1.0f);
}